// round 1
// baseline (speedup 1.0000x reference)
#include <cuda_runtime.h>
#include <cstdint>

// Problem constants
#define HN 2048   // hidden
#define EN 64     // experts
#define IN 1024   // expert intermediate
#define SIN 4096  // shared intermediate
#define KN 8      // top-k
#define TN 1024   // tokens

// ---------------- scratch (device globals: allocation-free) ----------------
__device__ int   g_cnt[EN];
__device__ int   g_off[EN];
__device__ int   g_list[EN * TN];        // entries: t*KN + k
__device__ float g_topv[TN * KN];        // sigmoid routing weights
__device__ float g_gu[TN * KN * 2 * IN]; // expert gate_up out  [8192, 2048]
__device__ float g_h[TN * KN * IN];      // expert hidden       [8192, 1024]
__device__ float g_moe[TN * KN * HN];    // expert out per pair [8192, 2048]
__device__ float g_gus[TN * 2 * SIN];    // shared gate_up      [1024, 8192]
__device__ float g_hs[TN * SIN];         // shared hidden       [1024, 4096]
__device__ float g_sh[TN * HN];          // shared out          [1024, 2048]

// ---------------- small helpers ----------------
__device__ __forceinline__ uint32_t f2tf(float f) {
    uint32_t u;
    asm("cvt.rna.tf32.f32 %0, %1;" : "=r"(u) : "f"(f));
    return u;
}

__device__ __forceinline__ void mma_tf32(float c[4], const uint32_t a[4], const uint32_t b[2]) {
    asm volatile(
        "mma.sync.aligned.m16n8k8.row.col.f32.tf32.tf32.f32 "
        "{%0,%1,%2,%3},{%4,%5,%6,%7},{%8,%9},{%0,%1,%2,%3};\n"
        : "+f"(c[0]), "+f"(c[1]), "+f"(c[2]), "+f"(c[3])
        : "r"(a[0]), "r"(a[1]), "r"(a[2]), "r"(a[3]), "r"(b[0]), "r"(b[1]));
}

// ---------------- init ----------------
__global__ void zero_cnt_kernel() {
    if (threadIdx.x < EN) g_cnt[threadIdx.x] = 0;
}

// ---------------- router: logits -> sigmoid top-8, build expert lists ------
__global__ void router_kernel(const float* __restrict__ x, const float* __restrict__ wg) {
    __shared__ float xs[HN];
    __shared__ float logits[EN];
    int t = blockIdx.x;
    for (int i = threadIdx.x; i < HN; i += blockDim.x) xs[i] = x[(size_t)t * HN + i];
    __syncthreads();
    int warp = threadIdx.x >> 5, lane = threadIdx.x & 31;
    for (int e = warp; e < EN; e += 8) {
        const float* w = wg + (size_t)e * HN;
        float s = 0.f;
        for (int i = lane; i < HN; i += 32) s += xs[i] * w[i];
        #pragma unroll
        for (int o = 16; o; o >>= 1) s += __shfl_xor_sync(0xffffffffu, s, o);
        if (lane == 0) logits[e] = s;
    }
    __syncthreads();
    if (threadIdx.x == 0) {
        #pragma unroll 1
        for (int k = 0; k < KN; k++) {
            int best = 0; float bv = -1e30f;
            for (int e = 0; e < EN; e++) {
                float v = logits[e];
                if (v > bv) { bv = v; best = e; }
            }
            logits[best] = -1e30f;
            g_topv[t * KN + k] = 1.f / (1.f + __expf(-bv));
            int slot = atomicAdd(&g_cnt[best], 1);
            g_list[best * TN + slot] = t * KN + k;
        }
    }
}

__global__ void offsets_kernel() {
    if (threadIdx.x == 0) {
        int s = 0;
        for (int e = 0; e < EN; e++) { g_off[e] = s; s += g_cnt[e]; }
    }
}

// ---------------- tiled tf32 GEMM: C[M,N] = A[M,K] * B[N,K]^T --------------
// MODE 0: plain (shared MLP).      A row = m, C row = m, M = Mfixed.
// MODE 1: expert gate_up.          A row = token(g_list), C row = compact,
//                                  B += e*strideB, M = g_cnt[e].
// MODE 2: expert down.             A row = compact, C row = g_list entry,
//                                  B += e*strideB, M = g_cnt[e].
#define BK 32
#define ROWPAD 36
#define ASTG (128 * ROWPAD)

template <int MODE>
__global__ void __launch_bounds__(256, 2)
gemm_tf32(const float* __restrict__ A, const float* __restrict__ Bw,
          float* __restrict__ C, int Kdim, int lda, int ldb, int ldc,
          int Mfixed, long long strideB)
{
    extern __shared__ float sm[];
    const int tid = threadIdx.x;
    const int e  = blockIdx.z;
    const int m0 = blockIdx.y * 128;
    const int n0 = blockIdx.x * 128;

    int M = Mfixed;
    const float* Bbase = Bw;
    int off_e = 0;
    if (MODE != 0) {
        M = g_cnt[e];
        if (m0 >= M) return;
        Bbase = Bw + (size_t)e * strideB;
        off_e = g_off[e];
    }

    // per-thread gmem source pointers (4 rows each for A and B tiles)
    const float* aptr[4];
    const float* bptr[4];
    #pragma unroll
    for (int it = 0; it < 4; ++it) {
        int r = (tid >> 3) + it * 32;
        int gr = m0 + r;
        const float* p = nullptr;
        if (gr < M) {
            if (MODE == 0)      p = A + (size_t)gr * lda;
            else if (MODE == 1) p = A + (size_t)(g_list[e * TN + gr] >> 3) * lda;
            else                p = A + (size_t)(off_e + gr) * lda;
            p += (tid & 7) * 4;
        }
        aptr[it] = p;
        bptr[it] = Bbase + (size_t)(n0 + r) * ldb + (tid & 7) * 4;
    }

    uint32_t sbase = (uint32_t)__cvta_generic_to_shared(sm);
    const int BOFF = 2 * ASTG;

    auto prefetch = [&](int buf, int k0) {
        #pragma unroll
        for (int it = 0; it < 4; ++it) {
            int r = (tid >> 3) + it * 32;
            uint32_t da = sbase + (uint32_t)((buf * ASTG + r * ROWPAD + (tid & 7) * 4) * 4);
            const void* src = aptr[it] ? (const void*)(aptr[it] + k0) : (const void*)A;
            int sz = aptr[it] ? 16 : 0;
            asm volatile("cp.async.cg.shared.global [%0], [%1], 16, %2;\n"
                         :: "r"(da), "l"(src), "r"(sz));
            uint32_t db = sbase + (uint32_t)((BOFF + buf * ASTG + r * ROWPAD + (tid & 7) * 4) * 4);
            asm volatile("cp.async.cg.shared.global [%0], [%1], 16;\n"
                         :: "r"(db), "l"(bptr[it] + k0));
        }
    };

    const int warp = tid >> 5, lane = tid & 31;
    const int wm = warp & 3, wn = warp >> 2;

    float acc[2][8][4];
    #pragma unroll
    for (int mf = 0; mf < 2; mf++)
        #pragma unroll
        for (int nf = 0; nf < 8; nf++)
            #pragma unroll
            for (int r = 0; r < 4; r++) acc[mf][nf][r] = 0.f;

    const int nK = Kdim >> 5;
    prefetch(0, 0);
    asm volatile("cp.async.commit_group;\n");

    for (int kt = 0; kt < nK; ++kt) {
        if (kt + 1 < nK) prefetch((kt + 1) & 1, (kt + 1) << 5);
        asm volatile("cp.async.commit_group;\n");
        asm volatile("cp.async.wait_group 1;\n");
        __syncthreads();

        const float* As = sm + (kt & 1) * ASTG;
        const float* Bs = sm + BOFF + (kt & 1) * ASTG;
        #pragma unroll
        for (int ks = 0; ks < 4; ++ks) {
            int kk = ks * 8 + (lane & 3);
            uint32_t af[2][4];
            uint32_t bf[8][2];
            #pragma unroll
            for (int mf = 0; mf < 2; ++mf) {
                int row = wm * 32 + mf * 16 + (lane >> 2);
                af[mf][0] = f2tf(As[row * ROWPAD + kk]);
                af[mf][1] = f2tf(As[(row + 8) * ROWPAD + kk]);
                af[mf][2] = f2tf(As[row * ROWPAD + kk + 4]);
                af[mf][3] = f2tf(As[(row + 8) * ROWPAD + kk + 4]);
            }
            #pragma unroll
            for (int nf = 0; nf < 8; ++nf) {
                int col = wn * 64 + nf * 8 + (lane >> 2);
                bf[nf][0] = f2tf(Bs[col * ROWPAD + kk]);
                bf[nf][1] = f2tf(Bs[col * ROWPAD + kk + 4]);
            }
            #pragma unroll
            for (int mf = 0; mf < 2; ++mf)
                #pragma unroll
                for (int nf = 0; nf < 8; ++nf)
                    mma_tf32(acc[mf][nf], af[mf], bf[nf]);
        }
        __syncthreads();
    }

    // epilogue
    #pragma unroll
    for (int mf = 0; mf < 2; ++mf) {
        #pragma unroll
        for (int half = 0; half < 2; ++half) {
            int rl = wm * 32 + mf * 16 + (lane >> 2) + half * 8;
            int gr = m0 + rl;
            if (gr >= M) continue;
            size_t crow;
            if (MODE == 0)      crow = (size_t)gr;
            else if (MODE == 1) crow = (size_t)(off_e + gr);
            else                crow = (size_t)g_list[e * TN + gr];
            float* cp = C + crow * (size_t)ldc + n0 + wn * 64 + (lane & 3) * 2;
            #pragma unroll
            for (int nf = 0; nf < 8; ++nf) {
                float2 v = make_float2(acc[mf][nf][half * 2], acc[mf][nf][half * 2 + 1]);
                *(float2*)(cp + nf * 8) = v;
            }
        }
    }
}

// ---------------- SiLU * mul ----------------
__global__ void silu_pairs_kernel() {
    int idx = blockIdx.x * 256 + threadIdx.x;          // [8192 * 1024]
    int r = idx >> 10, i = idx & 1023;
    float g = g_gu[(size_t)r * 2048 + i];
    float u = g_gu[(size_t)r * 2048 + 1024 + i];
    g_h[(size_t)r * 1024 + i] = g / (1.f + __expf(-g)) * u;
}

__global__ void silu_shared_kernel() {
    int idx = blockIdx.x * 256 + threadIdx.x;          // [1024 * 4096]
    int t = idx >> 12, i = idx & 4095;
    float g = g_gus[(size_t)t * 8192 + i];
    float u = g_gus[(size_t)t * 8192 + 4096 + i];
    g_hs[(size_t)t * 4096 + i] = g / (1.f + __expf(-g)) * u;
}

// ---------------- combine: (shared + K * sum_k w_k * moe_k) / (K+1) --------
__global__ void combine_kernel(float* __restrict__ out) {
    int idx = blockIdx.x * 256 + threadIdx.x;          // [1024 * 2048]
    int t = idx >> 11, d = idx & 2047;
    float acc = 0.f;
    #pragma unroll
    for (int k = 0; k < KN; k++)
        acc += g_topv[t * KN + k] * g_moe[(size_t)(t * KN + k) * HN + d];
    out[idx] = (g_sh[idx] + (float)KN * acc) * (1.f / (float)(KN + 1));
}

// ---------------- launch ----------------
extern "C" void kernel_launch(void* const* d_in, const int* in_sizes, int n_in,
                              void* d_out, int out_size)
{
    const float* x      = (const float*)d_in[0];  // [T,H]
    const float* w_gate = (const float*)d_in[1];  // [E,H]
    const float* w13    = (const float*)d_in[2];  // [E,2I,H]
    const float* w2     = (const float*)d_in[3];  // [E,H,I]
    const float* w_sgu  = (const float*)d_in[4];  // [2SI,H]
    const float* w_sdn  = (const float*)d_in[5];  // [H,SI]
    float* out = (float*)d_out;

    const int SMEM = 4 * ASTG * (int)sizeof(float);  // 73728 B
    cudaFuncSetAttribute(gemm_tf32<0>, cudaFuncAttributeMaxDynamicSharedMemorySize, SMEM);
    cudaFuncSetAttribute(gemm_tf32<1>, cudaFuncAttributeMaxDynamicSharedMemorySize, SMEM);
    cudaFuncSetAttribute(gemm_tf32<2>, cudaFuncAttributeMaxDynamicSharedMemorySize, SMEM);

    float *gu, *h, *moe, *gus, *hs, *sh;
    cudaGetSymbolAddress((void**)&gu,  g_gu);
    cudaGetSymbolAddress((void**)&h,   g_h);
    cudaGetSymbolAddress((void**)&moe, g_moe);
    cudaGetSymbolAddress((void**)&gus, g_gus);
    cudaGetSymbolAddress((void**)&hs,  g_hs);
    cudaGetSymbolAddress((void**)&sh,  g_sh);

    zero_cnt_kernel<<<1, 64>>>();
    router_kernel<<<TN, 256>>>(x, w_gate);
    offsets_kernel<<<1, 32>>>();

    // expert gate_up: C=gu [pairs, 2I], A=x gathered, B=w13[e] (2I x H)
    gemm_tf32<1><<<dim3(2 * IN / 128, 8, EN), 256, SMEM>>>(
        x, w13, gu, HN, HN, HN, 2 * IN, 0, (long long)2 * IN * HN);
    silu_pairs_kernel<<<(TN * KN * IN) / 256, 256>>>();

    // expert down: C=moe scattered to (t*K+k) rows, A=h compact, B=w2[e] (H x I)
    gemm_tf32<2><<<dim3(HN / 128, 8, EN), 256, SMEM>>>(
        h, w2, moe, IN, IN, IN, HN, 0, (long long)HN * IN);

    // shared gate_up: C=gus [T, 2SI]
    gemm_tf32<0><<<dim3(2 * SIN / 128, TN / 128, 1), 256, SMEM>>>(
        x, w_sgu, gus, HN, HN, HN, 2 * SIN, TN, 0);
    silu_shared_kernel<<<(TN * SIN) / 256, 256>>>();

    // shared down: C=sh [T, H]
    gemm_tf32<0><<<dim3(HN / 128, TN / 128, 1), 256, SMEM>>>(
        hs, w_sdn, sh, SIN, SIN, SIN, HN, TN, 0);

    combine_kernel<<<(TN * HN) / 256, 256>>>(out);
}

// round 4
// speedup vs baseline: 1.2545x; 1.2545x over previous
#include <cuda_runtime.h>
#include <cuda_fp16.h>
#include <cstdint>

// Problem constants
#define HN 2048   // hidden
#define EN 64     // experts
#define IN 1024   // expert intermediate
#define SIN 4096  // shared intermediate
#define KN 8      // top-k
#define TN 1024   // tokens

// ---------------- scratch (device globals: allocation-free) ----------------
__device__ int   g_cnt[EN];
__device__ int   g_off[EN];
__device__ int   g_list[EN * TN];        // entries: t*KN + k
__device__ float g_topv[TN * KN];        // sigmoid routing weights
__device__ float g_gu[TN * KN * 2 * IN]; // expert gate_up out  [8192, 2048]
__device__ float g_h[TN * KN * IN];      // expert hidden       [8192, 1024]
__device__ float g_moe[TN * KN * HN];    // expert out per pair [8192, 2048]
__device__ float g_gus[TN * 2 * SIN];    // shared gate_up      [1024, 8192]
__device__ float g_hs[TN * SIN];         // shared hidden       [1024, 4096]
__device__ float g_sh[TN * HN];          // shared out          [1024, 2048]

// ---------------- helpers ----------------
__device__ __forceinline__ void ldm4(uint32_t r[4], uint32_t a) {
    asm volatile("ldmatrix.sync.aligned.m8n8.x4.shared.b16 {%0,%1,%2,%3}, [%4];"
                 : "=r"(r[0]), "=r"(r[1]), "=r"(r[2]), "=r"(r[3]) : "r"(a));
}

__device__ __forceinline__ void mma16816(float c[4], const uint32_t a[4],
                                         uint32_t b0, uint32_t b1) {
    asm volatile(
        "mma.sync.aligned.m16n8k16.row.col.f32.f16.f16.f32 "
        "{%0,%1,%2,%3},{%4,%5,%6,%7},{%8,%9},{%0,%1,%2,%3};"
        : "+f"(c[0]), "+f"(c[1]), "+f"(c[2]), "+f"(c[3])
        : "r"(a[0]), "r"(a[1]), "r"(a[2]), "r"(a[3]), "r"(b0), "r"(b1));
}

__device__ __forceinline__ uint32_t smem_u32(const void* p) {
    uint32_t a;
    asm("{ .reg .u64 t; cvta.to.shared.u64 t, %1; cvt.u32.u64 %0, t; }" : "=r"(a) : "l"(p));
    return a;
}

__device__ __forceinline__ void sts64(uint32_t addr, uint2 v) {
    asm volatile("st.shared.v2.b32 [%0], {%1,%2};" :: "r"(addr), "r"(v.x), "r"(v.y) : "memory");
}

__device__ __forceinline__ uint2 f4_to_h4(float4 v) {
    __half2 lo = __float22half2_rn(make_float2(v.x, v.y));
    __half2 hi = __float22half2_rn(make_float2(v.z, v.w));
    uint2 r;
    r.x = *(uint32_t*)&lo;
    r.y = *(uint32_t*)&hi;
    return r;
}

// ---------------- init ----------------
__global__ void zero_cnt_kernel() {
    if (threadIdx.x < EN) g_cnt[threadIdx.x] = 0;
}

// ---------------- router ----------------
__global__ void router_kernel(const float* __restrict__ x, const float* __restrict__ wg) {
    __shared__ float xs[HN];
    __shared__ float logits[EN];
    int t = blockIdx.x;
    for (int i = threadIdx.x; i < HN; i += blockDim.x) xs[i] = x[(size_t)t * HN + i];
    __syncthreads();
    int warp = threadIdx.x >> 5, lane = threadIdx.x & 31;
    for (int e = warp; e < EN; e += 8) {
        const float* w = wg + (size_t)e * HN;
        float s = 0.f;
        for (int i = lane; i < HN; i += 32) s += xs[i] * w[i];
        #pragma unroll
        for (int o = 16; o; o >>= 1) s += __shfl_xor_sync(0xffffffffu, s, o);
        if (lane == 0) logits[e] = s;
    }
    __syncthreads();
    if (threadIdx.x == 0) {
        #pragma unroll 1
        for (int k = 0; k < KN; k++) {
            int best = 0; float bv = -1e30f;
            for (int e = 0; e < EN; e++) {
                float v = logits[e];
                if (v > bv) { bv = v; best = e; }
            }
            logits[best] = -1e30f;
            g_topv[t * KN + k] = 1.f / (1.f + __expf(-bv));
            int slot = atomicAdd(&g_cnt[best], 1);
            g_list[best * TN + slot] = t * KN + k;
        }
    }
}

__global__ void offsets_kernel() {
    if (threadIdx.x == 0) {
        int s = 0;
        for (int e = 0; e < EN; e++) { g_off[e] = s; s += g_cnt[e]; }
    }
}

// ---------------- fp16 tensor-core GEMM: C[M,N] = A[M,K] * B[N,K]^T -------
// MODE 0: plain (shared MLP).   A row = m, C row = m, M = Mfixed.
// MODE 1: expert gate_up.       A row = token(g_list), C row = compact.
// MODE 2: expert down.          A row = compact, C row = g_list entry.
//
// 128x128x32 tile, 256 threads (8 warps, 4x2), warp tile 32x64.
// smem: fp16 tiles, row pitch 80 B (64 B data + 16 pad) -> conflict-free
// ldmatrix. Register-staged pipeline: LDG f32 one stage ahead, convert to
// fp16 at STS time (one cvt per element).
#define APITCH 80
#define ATILE  (128 * APITCH)       // 10240 B
#define STG    (2 * ATILE)          // 20480 B per stage (A + B)
#define SMEM_G (2 * STG)            // 40960 B (double buffered)

template <int MODE>
__global__ void __launch_bounds__(256, 1)
gemm_f16(const float* __restrict__ A, const float* __restrict__ Bw,
         float* __restrict__ C, int Kdim, int lda, int ldb, int ldc,
         int Mfixed, long long strideB)
{
    extern __shared__ char smem[];
    const int tid = threadIdx.x;
    const int e  = blockIdx.z;
    const int m0 = blockIdx.y * 128;
    const int n0 = blockIdx.x * 128;

    int M = Mfixed;
    const float* Bbase = Bw;
    int off_e = 0;
    if (MODE != 0) {
        M = g_cnt[e];
        if (m0 >= M) return;
        Bbase = Bw + (size_t)e * strideB;
        off_e = g_off[e];
    }

    const uint32_t sbase = smem_u32(smem);

    // global source pointers: 4 rows A, 4 rows B per thread
    const float* aptr[4];
    const float* bptr[4];
    const int rbase = tid >> 3;
    const int kv4 = (tid & 7) * 4;
    #pragma unroll
    for (int i = 0; i < 4; ++i) {
        int r = rbase + i * 32;
        int gr = m0 + r;
        int src = (gr < M) ? gr : 0;   // clamp OOB rows (discarded at epilogue)
        const float* p;
        if (MODE == 0)      p = A + (size_t)gr * lda;
        else if (MODE == 1) p = A + (size_t)(g_list[e * TN + src] >> 3) * lda;
        else                p = A + (size_t)(off_e + src) * lda;
        aptr[i] = p + kv4;
        bptr[i] = Bbase + (size_t)(n0 + r) * ldb + kv4;
    }

    // smem store offsets (stage-invariant)
    uint32_t soff[4];
    #pragma unroll
    for (int i = 0; i < 4; ++i)
        soff[i] = (uint32_t)(rbase + i * 32) * APITCH + (uint32_t)(tid & 7) * 8;

    // ldmatrix lane offsets
    const int warp = tid >> 5, lane = tid & 31;
    const int wm = warp & 3, wn = warp >> 2;
    const int lrow = (lane & 7) + ((lane & 8) ? 8 : 0);
    const int lcol = (lane & 16) ? 16 : 0;
    uint32_t aoff[2], boff[4];
    #pragma unroll
    for (int mf = 0; mf < 2; ++mf)
        aoff[mf] = (uint32_t)(wm * 32 + mf * 16 + lrow) * APITCH + lcol;
    #pragma unroll
    for (int np = 0; np < 4; ++np)
        boff[np] = ATILE + (uint32_t)(wn * 64 + np * 16 + lrow) * APITCH + lcol;

    float acc[2][8][4];
    #pragma unroll
    for (int mf = 0; mf < 2; mf++)
        #pragma unroll
        for (int nf = 0; nf < 8; nf++)
            #pragma unroll
            for (int r = 0; r < 4; r++) acc[mf][nf][r] = 0.f;

    const int nK = Kdim >> 5;
    float4 ra[4], rb[4];

    // prologue: stage 0 -> buf0; prefetch stage 1
    #pragma unroll
    for (int i = 0; i < 4; ++i) { ra[i] = *(const float4*)(aptr[i]); rb[i] = *(const float4*)(bptr[i]); }
    #pragma unroll
    for (int i = 0; i < 4; ++i) {
        sts64(sbase + soff[i], f4_to_h4(ra[i]));
        sts64(sbase + ATILE + soff[i], f4_to_h4(rb[i]));
    }
    if (nK > 1) {
        #pragma unroll
        for (int i = 0; i < 4; ++i) { ra[i] = *(const float4*)(aptr[i] + 32); rb[i] = *(const float4*)(bptr[i] + 32); }
    }
    __syncthreads();

    for (int kt = 0; kt < nK; ++kt) {
        const uint32_t base = sbase + (uint32_t)(kt & 1) * STG;
        // store stage kt+1 into the other buffer; prefetch stage kt+2
        if (kt + 1 < nK) {
            const uint32_t nb = sbase + (uint32_t)((kt + 1) & 1) * STG;
            #pragma unroll
            for (int i = 0; i < 4; ++i) {
                sts64(nb + soff[i], f4_to_h4(ra[i]));
                sts64(nb + ATILE + soff[i], f4_to_h4(rb[i]));
            }
            if (kt + 2 < nK) {
                int k0 = (kt + 2) << 5;
                #pragma unroll
                for (int i = 0; i < 4; ++i) {
                    ra[i] = *(const float4*)(aptr[i] + k0);
                    rb[i] = *(const float4*)(bptr[i] + k0);
                }
            }
        }
        // compute on current buffer
        #pragma unroll
        for (int ks = 0; ks < 2; ++ks) {
            uint32_t af[2][4];
            ldm4(af[0], base + aoff[0] + ks * 32);
            ldm4(af[1], base + aoff[1] + ks * 32);
            uint32_t bf[4][4];
            #pragma unroll
            for (int np = 0; np < 4; ++np)
                ldm4(bf[np], base + boff[np] + ks * 32);
            // bf[np][0]=(n e0..7,k0..7) [1]=(n 8..15,k0..7) [2]=(n0..7,k8..15) [3]=(n8..15,k8..15)
            // mma needs b0 = same-n k0..7, b1 = same-n k8..15
            #pragma unroll
            for (int mf = 0; mf < 2; ++mf)
                #pragma unroll
                for (int nf = 0; nf < 8; ++nf)
                    mma16816(acc[mf][nf], af[mf],
                             bf[nf >> 1][nf & 1], bf[nf >> 1][(nf & 1) | 2]);
        }
        __syncthreads();
    }

    // epilogue
    #pragma unroll
    for (int mf = 0; mf < 2; ++mf) {
        #pragma unroll
        for (int half = 0; half < 2; ++half) {
            int rl = wm * 32 + mf * 16 + (lane >> 2) + half * 8;
            int gr = m0 + rl;
            if (gr >= M) continue;
            size_t crow;
            if (MODE == 0)      crow = (size_t)gr;
            else if (MODE == 1) crow = (size_t)(off_e + gr);
            else                crow = (size_t)g_list[e * TN + gr];
            float* cp = C + crow * (size_t)ldc + n0 + wn * 64 + (lane & 3) * 2;
            #pragma unroll
            for (int nf = 0; nf < 8; ++nf) {
                float2 v = make_float2(acc[mf][nf][half * 2], acc[mf][nf][half * 2 + 1]);
                *(float2*)(cp + nf * 8) = v;
            }
        }
    }
}

// ---------------- SiLU * mul ----------------
__global__ void silu_pairs_kernel() {
    int idx = blockIdx.x * 256 + threadIdx.x;          // [8192 * 1024]
    int r = idx >> 10, i = idx & 1023;
    float g = g_gu[(size_t)r * 2048 + i];
    float u = g_gu[(size_t)r * 2048 + 1024 + i];
    g_h[(size_t)r * 1024 + i] = g / (1.f + __expf(-g)) * u;
}

__global__ void silu_shared_kernel() {
    int idx = blockIdx.x * 256 + threadIdx.x;          // [1024 * 4096]
    int t = idx >> 12, i = idx & 4095;
    float g = g_gus[(size_t)t * 8192 + i];
    float u = g_gus[(size_t)t * 8192 + 4096 + i];
    g_hs[(size_t)t * 4096 + i] = g / (1.f + __expf(-g)) * u;
}

// ---------------- combine ----------------
__global__ void combine_kernel(float* __restrict__ out) {
    int idx = blockIdx.x * 256 + threadIdx.x;          // [1024 * 2048]
    int t = idx >> 11, d = idx & 2047;
    float acc = 0.f;
    #pragma unroll
    for (int k = 0; k < KN; k++)
        acc += g_topv[t * KN + k] * g_moe[(size_t)(t * KN + k) * HN + d];
    out[idx] = (g_sh[idx] + (float)KN * acc) * (1.f / (float)(KN + 1));
}

// ---------------- launch ----------------
extern "C" void kernel_launch(void* const* d_in, const int* in_sizes, int n_in,
                              void* d_out, int out_size)
{
    const float* x      = (const float*)d_in[0];  // [T,H]
    const float* w_gate = (const float*)d_in[1];  // [E,H]
    const float* w13    = (const float*)d_in[2];  // [E,2I,H]
    const float* w2     = (const float*)d_in[3];  // [E,H,I]
    const float* w_sgu  = (const float*)d_in[4];  // [2SI,H]
    const float* w_sdn  = (const float*)d_in[5];  // [H,SI]
    float* out = (float*)d_out;

    cudaFuncSetAttribute(gemm_f16<0>, cudaFuncAttributeMaxDynamicSharedMemorySize, SMEM_G);
    cudaFuncSetAttribute(gemm_f16<1>, cudaFuncAttributeMaxDynamicSharedMemorySize, SMEM_G);
    cudaFuncSetAttribute(gemm_f16<2>, cudaFuncAttributeMaxDynamicSharedMemorySize, SMEM_G);

    float *gu, *h, *moe, *gus, *hs, *sh;
    cudaGetSymbolAddress((void**)&gu,  g_gu);
    cudaGetSymbolAddress((void**)&h,   g_h);
    cudaGetSymbolAddress((void**)&moe, g_moe);
    cudaGetSymbolAddress((void**)&gus, g_gus);
    cudaGetSymbolAddress((void**)&hs,  g_hs);
    cudaGetSymbolAddress((void**)&sh,  g_sh);

    zero_cnt_kernel<<<1, 64>>>();
    router_kernel<<<TN, 256>>>(x, w_gate);
    offsets_kernel<<<1, 32>>>();

    // expert gate_up: C=gu [pairs, 2I], A=x gathered, B=w13[e] (2I x H), K=H
    gemm_f16<1><<<dim3(2 * IN / 128, 8, EN), 256, SMEM_G>>>(
        x, w13, gu, HN, HN, HN, 2 * IN, 0, (long long)2 * IN * HN);
    silu_pairs_kernel<<<(TN * KN * IN) / 256, 256>>>();

    // expert down: C=moe scattered, A=h compact, B=w2[e] (H x I), K=I
    gemm_f16<2><<<dim3(HN / 128, 8, EN), 256, SMEM_G>>>(
        h, w2, moe, IN, IN, IN, HN, 0, (long long)HN * IN);

    // shared gate_up: C=gus [T, 2SI], K=H
    gemm_f16<0><<<dim3(2 * SIN / 128, TN / 128, 1), 256, SMEM_G>>>(
        x, w_sgu, gus, HN, HN, HN, 2 * SIN, TN, 0);
    silu_shared_kernel<<<(TN * SIN) / 256, 256>>>();

    // shared down: C=sh [T, H], K=SI
    gemm_f16<0><<<dim3(HN / 128, TN / 128, 1), 256, SMEM_G>>>(
        hs, w_sdn, sh, SIN, SIN, SIN, HN, TN, 0);

    combine_kernel<<<(TN * HN) / 256, 256>>>(out);
}

// round 5
// speedup vs baseline: 1.2631x; 1.0068x over previous
#include <cuda_runtime.h>
#include <cuda_fp16.h>
#include <cstdint>

// Problem constants
#define HN 2048   // hidden
#define EN 64     // experts
#define IN 1024   // expert intermediate
#define SIN 4096  // shared intermediate
#define KN 8      // top-k
#define TN 1024   // tokens

// ---------------- scratch (device globals: allocation-free) ----------------
__device__ int   g_cnt[EN];
__device__ int   g_off[EN];
__device__ int   g_list[EN * TN];        // entries: t*KN + k
__device__ float g_topv[TN * KN];        // sigmoid routing weights
__device__ float g_gu[TN * KN * 2 * IN]; // expert gate_up out  [8192, 2048]
__device__ float g_h[TN * KN * IN];      // expert hidden       [8192, 1024]
__device__ float g_moe[TN * KN * HN];    // expert out per pair [8192, 2048]
__device__ float g_gus[TN * 2 * SIN];    // shared gate_up      [1024, 8192]
__device__ float g_hs[TN * SIN];         // shared hidden       [1024, 4096]
__device__ float g_sh[TN * HN];          // shared out          [1024, 2048]

// ---------------- helpers ----------------
__device__ __forceinline__ void ldm4(uint32_t r[4], uint32_t a) {
    asm volatile("ldmatrix.sync.aligned.m8n8.x4.shared.b16 {%0,%1,%2,%3}, [%4];"
                 : "=r"(r[0]), "=r"(r[1]), "=r"(r[2]), "=r"(r[3]) : "r"(a));
}

__device__ __forceinline__ void mma16816(float c[4], const uint32_t a[4],
                                         uint32_t b0, uint32_t b1) {
    asm volatile(
        "mma.sync.aligned.m16n8k16.row.col.f32.f16.f16.f32 "
        "{%0,%1,%2,%3},{%4,%5,%6,%7},{%8,%9},{%0,%1,%2,%3};"
        : "+f"(c[0]), "+f"(c[1]), "+f"(c[2]), "+f"(c[3])
        : "r"(a[0]), "r"(a[1]), "r"(a[2]), "r"(a[3]), "r"(b0), "r"(b1));
}

__device__ __forceinline__ uint32_t smem_u32(const void* p) {
    uint32_t a;
    asm("{ .reg .u64 t; cvta.to.shared.u64 t, %1; cvt.u32.u64 %0, t; }" : "=r"(a) : "l"(p));
    return a;
}

__device__ __forceinline__ void sts128(uint32_t addr, uint4 v) {
    asm volatile("st.shared.v4.b32 [%0], {%1,%2,%3,%4};"
                 :: "r"(addr), "r"(v.x), "r"(v.y), "r"(v.z), "r"(v.w) : "memory");
}

__device__ __forceinline__ uint32_t h2u(__half2 h) { return *(uint32_t*)&h; }

__device__ __forceinline__ uint4 f8_to_h8(float4 x, float4 y) {
    return make_uint4(
        h2u(__float22half2_rn(make_float2(x.x, x.y))),
        h2u(__float22half2_rn(make_float2(x.z, x.w))),
        h2u(__float22half2_rn(make_float2(y.x, y.y))),
        h2u(__float22half2_rn(make_float2(y.z, y.w))));
}

// 64B-pitch fp16 tile (128 rows x 32 halves), XOR swizzle on 16B chunks:
// off(r, c) = r*64 + ((c ^ ((r>>1)&3)) * 16).  Conflict-free for STS.128
// (8-lane phases: 2 rows -> banks 0-15 / 16-31) and LDSM (8-lane phases:
// even rows permute chunks across banks 0-15, odd rows across 16-31).
__device__ __forceinline__ uint32_t swz(uint32_t r, uint32_t c) {
    return r * 64u + (((c ^ ((r >> 1) & 3u)) << 4));
}

// ---------------- init ----------------
__global__ void zero_cnt_kernel() {
    if (threadIdx.x < EN) g_cnt[threadIdx.x] = 0;
}

// ---------------- router ----------------
__global__ void router_kernel(const float* __restrict__ x, const float* __restrict__ wg) {
    __shared__ float xs[HN];
    __shared__ float logits[EN];
    int t = blockIdx.x;
    for (int i = threadIdx.x; i < HN; i += blockDim.x) xs[i] = x[(size_t)t * HN + i];
    __syncthreads();
    int warp = threadIdx.x >> 5, lane = threadIdx.x & 31;
    for (int e = warp; e < EN; e += 8) {
        const float* w = wg + (size_t)e * HN;
        float s = 0.f;
        for (int i = lane; i < HN; i += 32) s += xs[i] * w[i];
        #pragma unroll
        for (int o = 16; o; o >>= 1) s += __shfl_xor_sync(0xffffffffu, s, o);
        if (lane == 0) logits[e] = s;
    }
    __syncthreads();
    if (threadIdx.x == 0) {
        #pragma unroll 1
        for (int k = 0; k < KN; k++) {
            int best = 0; float bv = -1e30f;
            for (int e = 0; e < EN; e++) {
                float v = logits[e];
                if (v > bv) { bv = v; best = e; }
            }
            logits[best] = -1e30f;
            g_topv[t * KN + k] = 1.f / (1.f + __expf(-bv));
            int slot = atomicAdd(&g_cnt[best], 1);
            g_list[best * TN + slot] = t * KN + k;
        }
    }
}

__global__ void offsets_kernel() {
    if (threadIdx.x == 0) {
        int s = 0;
        for (int e = 0; e < EN; e++) { g_off[e] = s; s += g_cnt[e]; }
    }
}

// ---------------- fp16 tensor-core GEMM: C[M,N] = A[M,K] * B[N,K]^T -------
// MODE 0: plain (shared MLP).   A row = m, C row = m, M = Mfixed.
// MODE 1: expert gate_up.       A row = token(g_list), C row = compact.
// MODE 2: expert down.          A row = compact, C row = g_list entry.
//
// 128x128x32 tile, 256 threads (8 warps 4x2, warp tile 32x64), 2 CTAs/SM.
// Double-buffered swizzled fp16 smem (8KB per tile, 32KB total).
// Next-stage LDG/cvt/STS interleaved between the two k-halves' MMA batches.
#define TILEB 8192               // one fp16 tile: 128 rows x 64 B
#define STGB  (2 * TILEB)        // stage = A + B tiles
#define SMEM_G (2 * STGB)        // 32768, double buffered

template <int MODE>
__global__ void __launch_bounds__(256, 2)
gemm_f16(const float* __restrict__ A, const float* __restrict__ Bw,
         float* __restrict__ C, int Kdim, int lda, int ldb, int ldc,
         int Mfixed, long long strideB)
{
    extern __shared__ char smem[];
    const int tid = threadIdx.x;
    const int e  = blockIdx.z;
    const int m0 = blockIdx.y * 128;
    const int n0 = blockIdx.x * 128;

    int M = Mfixed;
    const float* Bbase = Bw;
    int off_e = 0;
    if (MODE != 0) {
        M = g_cnt[e];
        if (m0 >= M) return;
        Bbase = Bw + (size_t)e * strideB;
        off_e = g_off[e];
    }

    const uint32_t sbase = smem_u32(smem);

    // ---- gmem load mapping: two 8-float segments each for A and B ----
    // segment s in {tid, tid+256}: row = s>>2, 16B-chunk c = s&3 (8 floats)
    const int rA0 = tid >> 2, rA1 = rA0 + 64;
    const int cseg = tid & 3;
    const float *pA0, *pA1, *pB0, *pB1;
    {
        int gr0 = m0 + rA0, gr1 = m0 + rA1;
        int s0 = (gr0 < M) ? gr0 : 0;
        int s1 = (gr1 < M) ? gr1 : 0;
        if (MODE == 0) {
            pA0 = A + (size_t)gr0 * lda;
            pA1 = A + (size_t)gr1 * lda;
        } else if (MODE == 1) {
            pA0 = A + (size_t)(g_list[e * TN + s0] >> 3) * lda;
            pA1 = A + (size_t)(g_list[e * TN + s1] >> 3) * lda;
        } else {
            pA0 = A + (size_t)(off_e + s0) * lda;
            pA1 = A + (size_t)(off_e + s1) * lda;
        }
        pA0 += cseg * 8; pA1 += cseg * 8;
        pB0 = Bbase + (size_t)(n0 + rA0) * ldb + cseg * 8;
        pB1 = Bbase + (size_t)(n0 + rA1) * ldb + cseg * 8;
    }
    const uint32_t soA0 = swz(rA0, cseg), soA1 = swz(rA1, cseg);
    const uint32_t soB0 = TILEB + soA0,   soB1 = TILEB + soA1;

    // ---- ldmatrix offsets (within a stage) ----
    const int warp = tid >> 5, lane = tid & 31;
    const int wm = warp & 3, wn = warp >> 2;
    const int l15 = lane & 15, chi = lane >> 4;
    uint32_t aoff[2][2], boff[4][2];
    #pragma unroll
    for (int mf = 0; mf < 2; ++mf) {
        uint32_t r = wm * 32 + mf * 16 + l15;
        #pragma unroll
        for (int ks = 0; ks < 2; ++ks) aoff[mf][ks] = swz(r, ks * 2 + chi);
    }
    #pragma unroll
    for (int np = 0; np < 4; ++np) {
        uint32_t r = wn * 64 + np * 16 + l15;
        #pragma unroll
        for (int ks = 0; ks < 2; ++ks) boff[np][ks] = TILEB + swz(r, ks * 2 + chi);
    }

    float acc[2][8][4];
    #pragma unroll
    for (int mf = 0; mf < 2; mf++)
        #pragma unroll
        for (int nf = 0; nf < 8; nf++)
            #pragma unroll
            for (int r = 0; r < 4; r++) acc[mf][nf][r] = 0.f;

    const int nK = Kdim >> 5;

    // load one 32-k stage into buffer dst
    auto load_stage = [&](uint32_t dst, int k0) {
        float4 a0 = *(const float4*)(pA0 + k0);
        float4 a1 = *(const float4*)(pA0 + k0 + 4);
        float4 a2 = *(const float4*)(pA1 + k0);
        float4 a3 = *(const float4*)(pA1 + k0 + 4);
        float4 b0 = *(const float4*)(pB0 + k0);
        float4 b1 = *(const float4*)(pB0 + k0 + 4);
        float4 b2 = *(const float4*)(pB1 + k0);
        float4 b3 = *(const float4*)(pB1 + k0 + 4);
        sts128(dst + soA0, f8_to_h8(a0, a1));
        sts128(dst + soA1, f8_to_h8(a2, a3));
        sts128(dst + soB0, f8_to_h8(b0, b1));
        sts128(dst + soB1, f8_to_h8(b2, b3));
    };

    load_stage(sbase, 0);
    __syncthreads();

    for (int kt = 0; kt < nK; ++kt) {
        const uint32_t base = sbase + (uint32_t)(kt & 1) * STGB;
        // ---- k-half 0 ----
        {
            uint32_t af[2][4], bf[4][4];
            ldm4(af[0], base + aoff[0][0]);
            ldm4(af[1], base + aoff[1][0]);
            #pragma unroll
            for (int np = 0; np < 4; ++np) ldm4(bf[np], base + boff[np][0]);
            #pragma unroll
            for (int mf = 0; mf < 2; ++mf)
                #pragma unroll
                for (int nf = 0; nf < 8; ++nf)
                    mma16816(acc[mf][nf], af[mf],
                             bf[nf >> 1][nf & 1], bf[nf >> 1][(nf & 1) | 2]);
        }
        // ---- fetch next stage (latency covered by queued MMAs + other warps) ----
        if (kt + 1 < nK)
            load_stage(sbase + (uint32_t)((kt + 1) & 1) * STGB, (kt + 1) << 5);
        // ---- k-half 1 ----
        {
            uint32_t af[2][4], bf[4][4];
            ldm4(af[0], base + aoff[0][1]);
            ldm4(af[1], base + aoff[1][1]);
            #pragma unroll
            for (int np = 0; np < 4; ++np) ldm4(bf[np], base + boff[np][1]);
            #pragma unroll
            for (int mf = 0; mf < 2; ++mf)
                #pragma unroll
                for (int nf = 0; nf < 8; ++nf)
                    mma16816(acc[mf][nf], af[mf],
                             bf[nf >> 1][nf & 1], bf[nf >> 1][(nf & 1) | 2]);
        }
        __syncthreads();
    }

    // epilogue
    #pragma unroll
    for (int mf = 0; mf < 2; ++mf) {
        #pragma unroll
        for (int half = 0; half < 2; ++half) {
            int rl = wm * 32 + mf * 16 + (lane >> 2) + half * 8;
            int gr = m0 + rl;
            if (gr >= M) continue;
            size_t crow;
            if (MODE == 0)      crow = (size_t)gr;
            else if (MODE == 1) crow = (size_t)(off_e + gr);
            else                crow = (size_t)g_list[e * TN + gr];
            float* cp = C + crow * (size_t)ldc + n0 + wn * 64 + (lane & 3) * 2;
            #pragma unroll
            for (int nf = 0; nf < 8; ++nf) {
                float2 v = make_float2(acc[mf][nf][half * 2], acc[mf][nf][half * 2 + 1]);
                *(float2*)(cp + nf * 8) = v;
            }
        }
    }
}

// ---------------- SiLU * mul ----------------
__global__ void silu_pairs_kernel() {
    int idx = blockIdx.x * 256 + threadIdx.x;          // [8192 * 1024]
    int r = idx >> 10, i = idx & 1023;
    float g = g_gu[(size_t)r * 2048 + i];
    float u = g_gu[(size_t)r * 2048 + 1024 + i];
    g_h[(size_t)r * 1024 + i] = g / (1.f + __expf(-g)) * u;
}

__global__ void silu_shared_kernel() {
    int idx = blockIdx.x * 256 + threadIdx.x;          // [1024 * 4096]
    int t = idx >> 12, i = idx & 4095;
    float g = g_gus[(size_t)t * 8192 + i];
    float u = g_gus[(size_t)t * 8192 + 4096 + i];
    g_hs[(size_t)t * 4096 + i] = g / (1.f + __expf(-g)) * u;
}

// ---------------- combine ----------------
__global__ void combine_kernel(float* __restrict__ out) {
    int idx = blockIdx.x * 256 + threadIdx.x;          // [1024 * 2048]
    int t = idx >> 11, d = idx & 2047;
    float acc = 0.f;
    #pragma unroll
    for (int k = 0; k < KN; k++)
        acc += g_topv[t * KN + k] * g_moe[(size_t)(t * KN + k) * HN + d];
    out[idx] = (g_sh[idx] + (float)KN * acc) * (1.f / (float)(KN + 1));
}

// ---------------- launch ----------------
extern "C" void kernel_launch(void* const* d_in, const int* in_sizes, int n_in,
                              void* d_out, int out_size)
{
    const float* x      = (const float*)d_in[0];  // [T,H]
    const float* w_gate = (const float*)d_in[1];  // [E,H]
    const float* w13    = (const float*)d_in[2];  // [E,2I,H]
    const float* w2     = (const float*)d_in[3];  // [E,H,I]
    const float* w_sgu  = (const float*)d_in[4];  // [2SI,H]
    const float* w_sdn  = (const float*)d_in[5];  // [H,SI]
    float* out = (float*)d_out;

    cudaFuncSetAttribute(gemm_f16<0>, cudaFuncAttributeMaxDynamicSharedMemorySize, SMEM_G);
    cudaFuncSetAttribute(gemm_f16<1>, cudaFuncAttributeMaxDynamicSharedMemorySize, SMEM_G);
    cudaFuncSetAttribute(gemm_f16<2>, cudaFuncAttributeMaxDynamicSharedMemorySize, SMEM_G);

    float *gu, *h, *moe, *gus, *hs, *sh;
    cudaGetSymbolAddress((void**)&gu,  g_gu);
    cudaGetSymbolAddress((void**)&h,   g_h);
    cudaGetSymbolAddress((void**)&moe, g_moe);
    cudaGetSymbolAddress((void**)&gus, g_gus);
    cudaGetSymbolAddress((void**)&hs,  g_hs);
    cudaGetSymbolAddress((void**)&sh,  g_sh);

    zero_cnt_kernel<<<1, 64>>>();
    router_kernel<<<TN, 256>>>(x, w_gate);
    offsets_kernel<<<1, 32>>>();

    // expert gate_up: C=gu [pairs, 2I], A=x gathered, B=w13[e] (2I x H), K=H
    gemm_f16<1><<<dim3(2 * IN / 128, 8, EN), 256, SMEM_G>>>(
        x, w13, gu, HN, HN, HN, 2 * IN, 0, (long long)2 * IN * HN);
    silu_pairs_kernel<<<(TN * KN * IN) / 256, 256>>>();

    // expert down: C=moe scattered, A=h compact, B=w2[e] (H x I), K=I
    gemm_f16<2><<<dim3(HN / 128, 8, EN), 256, SMEM_G>>>(
        h, w2, moe, IN, IN, IN, HN, 0, (long long)HN * IN);

    // shared gate_up: C=gus [T, 2SI], K=H
    gemm_f16<0><<<dim3(2 * SIN / 128, TN / 128, 1), 256, SMEM_G>>>(
        x, w_sgu, gus, HN, HN, HN, 2 * SIN, TN, 0);
    silu_shared_kernel<<<(TN * SIN) / 256, 256>>>();

    // shared down: C=sh [T, H], K=SI
    gemm_f16<0><<<dim3(HN / 128, TN / 128, 1), 256, SMEM_G>>>(
        hs, w_sdn, sh, SIN, SIN, SIN, HN, TN, 0);

    combine_kernel<<<(TN * HN) / 256, 256>>>(out);
}

// round 7
// speedup vs baseline: 1.5345x; 1.2149x over previous
#include <cuda_runtime.h>
#include <cuda_fp16.h>
#include <cstdint>

// Problem constants
#define HN 2048   // hidden
#define EN 64     // experts
#define IN 1024   // expert intermediate
#define SIN 4096  // shared intermediate
#define KN 8      // top-k
#define TN 1024   // tokens

// ---------------- scratch (device globals: allocation-free) ----------------
__device__ int   g_cnt[EN];
__device__ int   g_off[EN];
__device__ int   g_list[EN * TN];        // entries: t*KN + k
__device__ float g_topv[TN * KN];        // sigmoid routing weights
__device__ float g_gu[TN * KN * 2 * IN]; // expert gate_up out  [8192, 2048]
__device__ float g_h[TN * KN * IN];      // expert hidden       [8192, 1024]
__device__ float g_moe[TN * KN * HN];    // expert out per pair [8192, 2048]
__device__ float g_gus[TN * 2 * SIN];    // shared gate_up      [1024, 8192]
__device__ float g_hs[TN * SIN];         // shared hidden       [1024, 4096]
__device__ float g_sh[TN * HN];          // shared out          [1024, 2048]

// ---------------- helpers ----------------
__device__ __forceinline__ void ldm4(uint32_t r[4], uint32_t a) {
    asm volatile("ldmatrix.sync.aligned.m8n8.x4.shared.b16 {%0,%1,%2,%3}, [%4];"
                 : "=r"(r[0]), "=r"(r[1]), "=r"(r[2]), "=r"(r[3]) : "r"(a));
}

__device__ __forceinline__ void mma16816(float c[4], const uint32_t a[4],
                                         uint32_t b0, uint32_t b1) {
    asm volatile(
        "mma.sync.aligned.m16n8k16.row.col.f32.f16.f16.f32 "
        "{%0,%1,%2,%3},{%4,%5,%6,%7},{%8,%9},{%0,%1,%2,%3};"
        : "+f"(c[0]), "+f"(c[1]), "+f"(c[2]), "+f"(c[3])
        : "r"(a[0]), "r"(a[1]), "r"(a[2]), "r"(a[3]), "r"(b0), "r"(b1));
}

__device__ __forceinline__ uint32_t smem_u32(const void* p) {
    uint32_t a;
    asm("{ .reg .u64 t; cvta.to.shared.u64 t, %1; cvt.u32.u64 %0, t; }" : "=r"(a) : "l"(p));
    return a;
}

__device__ __forceinline__ void sts128(uint32_t addr, uint4 v) {
    asm volatile("st.shared.v4.b32 [%0], {%1,%2,%3,%4};"
                 :: "r"(addr), "r"(v.x), "r"(v.y), "r"(v.z), "r"(v.w) : "memory");
}

__device__ __forceinline__ uint32_t h2u(__half2 h) { return *(uint32_t*)&h; }

__device__ __forceinline__ uint4 f8_to_h8(float4 x, float4 y) {
    return make_uint4(
        h2u(__float22half2_rn(make_float2(x.x, x.y))),
        h2u(__float22half2_rn(make_float2(x.z, x.w))),
        h2u(__float22half2_rn(make_float2(y.x, y.y))),
        h2u(__float22half2_rn(make_float2(y.z, y.w))));
}

// 64B-pitch fp16 tile (rows x 32 halves), XOR swizzle on 16B chunks:
// off(r, c) = r*64 + ((c ^ ((r>>1)&3)) * 16).  Conflict-free for STS.128
// and LDSM 8-lane phases.
__device__ __forceinline__ uint32_t swz(uint32_t r, uint32_t c) {
    return r * 64u + (((c ^ ((r >> 1) & 3u)) << 4));
}

// ---------------- init ----------------
__global__ void zero_cnt_kernel() {
    if (threadIdx.x < EN) g_cnt[threadIdx.x] = 0;
}

// ---------------- router ----------------
__global__ void router_kernel(const float* __restrict__ x, const float* __restrict__ wg) {
    __shared__ float xs[HN];
    __shared__ float logits[EN];
    int t = blockIdx.x;
    for (int i = threadIdx.x; i < HN; i += blockDim.x) xs[i] = x[(size_t)t * HN + i];
    __syncthreads();
    int warp = threadIdx.x >> 5, lane = threadIdx.x & 31;
    for (int e = warp; e < EN; e += 8) {
        const float* w = wg + (size_t)e * HN;
        float s = 0.f;
        for (int i = lane; i < HN; i += 32) s += xs[i] * w[i];
        #pragma unroll
        for (int o = 16; o; o >>= 1) s += __shfl_xor_sync(0xffffffffu, s, o);
        if (lane == 0) logits[e] = s;
    }
    __syncthreads();
    if (threadIdx.x == 0) {
        #pragma unroll 1
        for (int k = 0; k < KN; k++) {
            int best = 0; float bv = -1e30f;
            for (int e = 0; e < EN; e++) {
                float v = logits[e];
                if (v > bv) { bv = v; best = e; }
            }
            logits[best] = -1e30f;
            g_topv[t * KN + k] = 1.f / (1.f + __expf(-bv));
            int slot = atomicAdd(&g_cnt[best], 1);
            g_list[best * TN + slot] = t * KN + k;
        }
    }
}

__global__ void offsets_kernel() {
    if (threadIdx.x == 0) {
        int s = 0;
        for (int e = 0; e < EN; e++) { g_off[e] = s; s += g_cnt[e]; }
    }
}

// ---------------- fp16 tensor-core GEMM: C[M,N] = A[M,K] * B[N,K]^T -------
// MODE 0: plain (shared MLP).   A row = m, C row = m, M = Mfixed.
// MODE 1: expert gate_up.       A row = token(g_list), C row = compact.
// MODE 2: expert down.          A row = compact, C row = g_list entry.
//
// CTA tile 128(M) x 256(N) x 32(K), 256 threads, warp grid 2x4,
// warp tile 64x64 (128 acc regs) -> ~133 smem-bytes per MMA (tensor-bound).
// Double-buffered swizzled fp16 smem: A 8KB + B 16KB per stage, 48KB total.
// Register-staged global prefetch one full stage ahead.
#define ASTAGE 8192               // A tile: 128 rows x 64 B
#define BSTAGE 16384              // B tile: 256 rows x 64 B
#define STGB   (ASTAGE + BSTAGE)  // 24576
#define SMEM_G (2 * STGB)         // 49152

template <int MODE>
__global__ void __launch_bounds__(256, 1)
gemm_f16(const float* __restrict__ A, const float* __restrict__ Bw,
         float* __restrict__ C, int Kdim, int lda, int ldb, int ldc,
         int Mfixed, long long strideB)
{
    extern __shared__ char smem[];
    const int tid = threadIdx.x;
    const int e  = blockIdx.z;
    const int m0 = blockIdx.y * 128;
    const int n0 = blockIdx.x * 256;

    int M = Mfixed;
    const float* Bbase = Bw;
    int off_e = 0;
    if (MODE != 0) {
        M = g_cnt[e];
        if (m0 >= M) return;
        Bbase = Bw + (size_t)e * strideB;
        off_e = g_off[e];
    }

    const uint32_t sbase = smem_u32(smem);

    // ---- gmem load mapping ----
    // A: 128 rows, rows tid>>2 and tid>>2+64, 16B-chunk tid&3 (8 f32 each)
    // B: 256 rows, rows tid>>2 + 64j (j=0..3), chunk tid&3
    const int rbase = tid >> 2;
    const int cseg = tid & 3;
    const float* pA[2];
    const float* pB[4];
    uint32_t soA[2], soB[4];
    #pragma unroll
    for (int i = 0; i < 2; ++i) {
        int r = rbase + i * 64;
        int gr = m0 + r;
        int src = (gr < M) ? gr : 0;   // clamp OOB rows (discarded at epilogue)
        const float* p;
        if (MODE == 0)      p = A + (size_t)gr * lda;
        else if (MODE == 1) p = A + (size_t)(g_list[e * TN + src] >> 3) * lda;
        else                p = A + (size_t)(off_e + src) * lda;
        pA[i] = p + cseg * 8;
        soA[i] = swz((uint32_t)r, (uint32_t)cseg);
    }
    #pragma unroll
    for (int j = 0; j < 4; ++j) {
        int r = rbase + j * 64;
        pB[j] = Bbase + (size_t)(n0 + r) * ldb + cseg * 8;
        soB[j] = ASTAGE + swz((uint32_t)r, (uint32_t)cseg);
    }

    // ---- ldmatrix offsets (within a stage) ----
    const int warp = tid >> 5, lane = tid & 31;
    const int wm = warp & 1, wn = warp >> 1;          // 2 x 4 warp grid
    const int l15 = lane & 15, chi = lane >> 4;
    uint32_t aoff[4][2], boff[4][2];
    #pragma unroll
    for (int mf = 0; mf < 4; ++mf) {
        uint32_t r = wm * 64 + mf * 16 + l15;
        #pragma unroll
        for (int ks = 0; ks < 2; ++ks) aoff[mf][ks] = swz(r, ks * 2 + chi);
    }
    #pragma unroll
    for (int np = 0; np < 4; ++np) {
        uint32_t r = wn * 64 + np * 16 + l15;
        #pragma unroll
        for (int ks = 0; ks < 2; ++ks) boff[np][ks] = ASTAGE + swz(r, ks * 2 + chi);
    }

    float acc[4][8][4];
    #pragma unroll
    for (int mf = 0; mf < 4; mf++)
        #pragma unroll
        for (int nf = 0; nf < 8; nf++)
            #pragma unroll
            for (int r = 0; r < 4; r++) acc[mf][nf][r] = 0.f;

    const int nK = Kdim >> 5;

    // staging registers: A 2 segs x 8 f32, B 4 segs x 8 f32
    float4 ra[2][2], rb[4][2];

    auto fetch = [&](int k0) {
        #pragma unroll
        for (int i = 0; i < 2; ++i) {
            ra[i][0] = *(const float4*)(pA[i] + k0);
            ra[i][1] = *(const float4*)(pA[i] + k0 + 4);
        }
        #pragma unroll
        for (int j = 0; j < 4; ++j) {
            rb[j][0] = *(const float4*)(pB[j] + k0);
            rb[j][1] = *(const float4*)(pB[j] + k0 + 4);
        }
    };
    auto store_stage = [&](uint32_t dst) {
        #pragma unroll
        for (int i = 0; i < 2; ++i)
            sts128(dst + soA[i], f8_to_h8(ra[i][0], ra[i][1]));
        #pragma unroll
        for (int j = 0; j < 4; ++j)
            sts128(dst + soB[j], f8_to_h8(rb[j][0], rb[j][1]));
    };

    // prologue: stage 0 -> buf0; prefetch stage 1 into regs
    fetch(0);
    store_stage(sbase);
    if (nK > 1) fetch(32);
    __syncthreads();

    for (int kt = 0; kt < nK; ++kt) {
        const uint32_t base = sbase + (uint32_t)(kt & 1) * STGB;
        // ---- k-half 0 ----
        {
            uint32_t af[4][4], bf[4][4];
            #pragma unroll
            for (int mf = 0; mf < 4; ++mf) ldm4(af[mf], base + aoff[mf][0]);
            #pragma unroll
            for (int np = 0; np < 4; ++np) ldm4(bf[np], base + boff[np][0]);
            #pragma unroll
            for (int mf = 0; mf < 4; ++mf)
                #pragma unroll
                for (int nf = 0; nf < 8; ++nf)
                    mma16816(acc[mf][nf], af[mf],
                             bf[nf >> 1][nf & 1], bf[nf >> 1][(nf & 1) | 2]);
        }
        // ---- drain staged regs into other buffer; prefetch stage kt+2 ----
        if (kt + 1 < nK) {
            store_stage(sbase + (uint32_t)((kt + 1) & 1) * STGB);
            if (kt + 2 < nK) fetch((kt + 2) << 5);
        }
        // ---- k-half 1 ----
        {
            uint32_t af[4][4], bf[4][4];
            #pragma unroll
            for (int mf = 0; mf < 4; ++mf) ldm4(af[mf], base + aoff[mf][1]);
            #pragma unroll
            for (int np = 0; np < 4; ++np) ldm4(bf[np], base + boff[np][1]);
            #pragma unroll
            for (int mf = 0; mf < 4; ++mf)
                #pragma unroll
                for (int nf = 0; nf < 8; ++nf)
                    mma16816(acc[mf][nf], af[mf],
                             bf[nf >> 1][nf & 1], bf[nf >> 1][(nf & 1) | 2]);
        }
        __syncthreads();
    }

    // epilogue: warp rows wm*64 + mf*16 + lane>>2 (+8), cols n0 + wn*64 + nf*8
    #pragma unroll
    for (int mf = 0; mf < 4; ++mf) {
        #pragma unroll
        for (int half = 0; half < 2; ++half) {
            int rl = wm * 64 + mf * 16 + (lane >> 2) + half * 8;
            int gr = m0 + rl;
            if (gr >= M) continue;
            size_t crow;
            if (MODE == 0)      crow = (size_t)gr;
            else if (MODE == 1) crow = (size_t)(off_e + gr);
            else                crow = (size_t)g_list[e * TN + gr];
            float* cp = C + crow * (size_t)ldc + n0 + wn * 64 + (lane & 3) * 2;
            #pragma unroll
            for (int nf = 0; nf < 8; ++nf) {
                float2 v = make_float2(acc[mf][nf][half * 2], acc[mf][nf][half * 2 + 1]);
                *(float2*)(cp + nf * 8) = v;
            }
        }
    }
}

// ---------------- SiLU * mul (float4 vectorized) ----------------
__global__ void silu_pairs_kernel() {
    int idx = blockIdx.x * 256 + threadIdx.x;          // over [8192 * 256] float4
    int r = idx >> 8, i = (idx & 255) * 4;
    float4 g = *(const float4*)&g_gu[(size_t)r * 2048 + i];
    float4 u = *(const float4*)&g_gu[(size_t)r * 2048 + 1024 + i];
    float4 o;
    o.x = g.x / (1.f + __expf(-g.x)) * u.x;
    o.y = g.y / (1.f + __expf(-g.y)) * u.y;
    o.z = g.z / (1.f + __expf(-g.z)) * u.z;
    o.w = g.w / (1.f + __expf(-g.w)) * u.w;
    *(float4*)&g_h[(size_t)r * 1024 + i] = o;
}

__global__ void silu_shared_kernel() {
    int idx = blockIdx.x * 256 + threadIdx.x;          // over [1024 * 1024] float4
    int t = idx >> 10, i = (idx & 1023) * 4;
    float4 g = *(const float4*)&g_gus[(size_t)t * 8192 + i];
    float4 u = *(const float4*)&g_gus[(size_t)t * 8192 + 4096 + i];
    float4 o;
    o.x = g.x / (1.f + __expf(-g.x)) * u.x;
    o.y = g.y / (1.f + __expf(-g.y)) * u.y;
    o.z = g.z / (1.f + __expf(-g.z)) * u.z;
    o.w = g.w / (1.f + __expf(-g.w)) * u.w;
    *(float4*)&g_hs[(size_t)t * 4096 + i] = o;
}

// ---------------- combine ----------------
__global__ void combine_kernel(float* __restrict__ out) {
    int idx = blockIdx.x * 256 + threadIdx.x;          // over [1024 * 512] float4
    int t = idx >> 9, d = (idx & 511) * 4;
    float4 acc = make_float4(0.f, 0.f, 0.f, 0.f);
    #pragma unroll
    for (int k = 0; k < KN; k++) {
        float w = g_topv[t * KN + k];
        float4 m = *(const float4*)&g_moe[(size_t)(t * KN + k) * HN + d];
        acc.x += w * m.x; acc.y += w * m.y; acc.z += w * m.z; acc.w += w * m.w;
    }
    float4 s = *(const float4*)&g_sh[(size_t)t * HN + d];
    const float inv = 1.f / (float)(KN + 1);
    float4 o;
    o.x = (s.x + KN * acc.x) * inv;
    o.y = (s.y + KN * acc.y) * inv;
    o.z = (s.z + KN * acc.z) * inv;
    o.w = (s.w + KN * acc.w) * inv;
    *(float4*)&out[(size_t)t * HN + d] = o;
}

// ---------------- launch ----------------
extern "C" void kernel_launch(void* const* d_in, const int* in_sizes, int n_in,
                              void* d_out, int out_size)
{
    const float* x      = (const float*)d_in[0];  // [T,H]
    const float* w_gate = (const float*)d_in[1];  // [E,H]
    const float* w13    = (const float*)d_in[2];  // [E,2I,H]
    const float* w2     = (const float*)d_in[3];  // [E,H,I]
    const float* w_sgu  = (const float*)d_in[4];  // [2SI,H]
    const float* w_sdn  = (const float*)d_in[5];  // [H,SI]
    float* out = (float*)d_out;

    cudaFuncSetAttribute(gemm_f16<0>, cudaFuncAttributeMaxDynamicSharedMemorySize, SMEM_G);
    cudaFuncSetAttribute(gemm_f16<1>, cudaFuncAttributeMaxDynamicSharedMemorySize, SMEM_G);
    cudaFuncSetAttribute(gemm_f16<2>, cudaFuncAttributeMaxDynamicSharedMemorySize, SMEM_G);

    float *gu, *h, *moe, *gus, *hs, *sh;
    cudaGetSymbolAddress((void**)&gu,  g_gu);
    cudaGetSymbolAddress((void**)&h,   g_h);
    cudaGetSymbolAddress((void**)&moe, g_moe);
    cudaGetSymbolAddress((void**)&gus, g_gus);
    cudaGetSymbolAddress((void**)&hs,  g_hs);
    cudaGetSymbolAddress((void**)&sh,  g_sh);

    zero_cnt_kernel<<<1, 64>>>();
    router_kernel<<<TN, 256>>>(x, w_gate);
    offsets_kernel<<<1, 32>>>();

    // expert gate_up: C=gu [pairs, 2I], A=x gathered, B=w13[e] (2I x H), K=H
    gemm_f16<1><<<dim3(2 * IN / 256, 8, EN), 256, SMEM_G>>>(
        x, w13, gu, HN, HN, HN, 2 * IN, 0, (long long)2 * IN * HN);
    silu_pairs_kernel<<<(TN * KN * IN / 4) / 256, 256>>>();

    // expert down: C=moe scattered, A=h compact, B=w2[e] (H x I), K=I
    gemm_f16<2><<<dim3(HN / 256, 8, EN), 256, SMEM_G>>>(
        h, w2, moe, IN, IN, IN, HN, 0, (long long)HN * IN);

    // shared gate_up: C=gus [T, 2SI], K=H
    gemm_f16<0><<<dim3(2 * SIN / 256, TN / 128, 1), 256, SMEM_G>>>(
        x, w_sgu, gus, HN, HN, HN, 2 * SIN, TN, 0);
    silu_shared_kernel<<<(TN * SIN / 4) / 256, 256>>>();

    // shared down: C=sh [T, H], K=SI
    gemm_f16<0><<<dim3(HN / 256, TN / 128, 1), 256, SMEM_G>>>(
        hs, w_sdn, sh, SIN, SIN, SIN, HN, TN, 0);

    combine_kernel<<<(TN * HN / 4) / 256, 256>>>(out);
}

// round 8
// speedup vs baseline: 1.5587x; 1.0157x over previous
#include <cuda_runtime.h>
#include <cuda_fp16.h>
#include <cstdint>

// Problem constants
#define HN 2048   // hidden
#define EN 64     // experts
#define IN 1024   // expert intermediate
#define SIN 4096  // shared intermediate
#define KN 8      // top-k
#define TN 1024   // tokens

// ---------------- scratch (device globals: allocation-free) ----------------
__device__ int    g_cnt[EN];
__device__ int    g_off[EN];
__device__ int    g_list[EN * TN];        // entries: t*KN + k
__device__ float  g_topv[TN * KN];        // sigmoid routing weights
__device__ __half g_xh[TN * HN];          // fp16 copy of x
__device__ __half g_h[TN * KN * IN];      // expert hidden (fp16)   [8192, 1024]
__device__ float  g_moe[TN * KN * HN];    // expert out per pair    [8192, 2048]
__device__ __half g_hs[TN * SIN];         // shared hidden (fp16)   [1024, 4096]
__device__ float  g_sh[TN * HN];          // shared out             [1024, 2048]

// ---------------- helpers ----------------
__device__ __forceinline__ void ldm4(uint32_t r[4], uint32_t a) {
    asm volatile("ldmatrix.sync.aligned.m8n8.x4.shared.b16 {%0,%1,%2,%3}, [%4];"
                 : "=r"(r[0]), "=r"(r[1]), "=r"(r[2]), "=r"(r[3]) : "r"(a));
}

__device__ __forceinline__ void mma16816(float c[4], const uint32_t a[4],
                                         uint32_t b0, uint32_t b1) {
    asm volatile(
        "mma.sync.aligned.m16n8k16.row.col.f32.f16.f16.f32 "
        "{%0,%1,%2,%3},{%4,%5,%6,%7},{%8,%9},{%0,%1,%2,%3};"
        : "+f"(c[0]), "+f"(c[1]), "+f"(c[2]), "+f"(c[3])
        : "r"(a[0]), "r"(a[1]), "r"(a[2]), "r"(a[3]), "r"(b0), "r"(b1));
}

__device__ __forceinline__ uint32_t smem_u32(const void* p) {
    uint32_t a;
    asm("{ .reg .u64 t; cvta.to.shared.u64 t, %1; cvt.u32.u64 %0, t; }" : "=r"(a) : "l"(p));
    return a;
}

__device__ __forceinline__ void sts128(uint32_t addr, uint4 v) {
    asm volatile("st.shared.v4.b32 [%0], {%1,%2,%3,%4};"
                 :: "r"(addr), "r"(v.x), "r"(v.y), "r"(v.z), "r"(v.w) : "memory");
}

__device__ __forceinline__ uint32_t h2u(__half2 h) { return *(uint32_t*)&h; }

__device__ __forceinline__ uint4 f8_to_h8(float4 x, float4 y) {
    return make_uint4(
        h2u(__float22half2_rn(make_float2(x.x, x.y))),
        h2u(__float22half2_rn(make_float2(x.z, x.w))),
        h2u(__float22half2_rn(make_float2(y.x, y.y))),
        h2u(__float22half2_rn(make_float2(y.z, y.w))));
}

// 64B-pitch fp16 tile (rows x 32 halves), XOR swizzle on 16B chunks:
// off(r, c) = r*64 + ((c ^ ((r>>1)&3)) * 16). Conflict-free for STS.128 and LDSM.
__device__ __forceinline__ uint32_t swz(uint32_t r, uint32_t c) {
    return r * 64u + (((c ^ ((r >> 1) & 3u)) << 4));
}

// ---------------- init / convert ----------------
__global__ void zero_cnt_kernel() {
    if (threadIdx.x < EN) g_cnt[threadIdx.x] = 0;
}

__global__ void cvt_x_kernel(const float* __restrict__ x) {
    int idx = blockIdx.x * 256 + threadIdx.x;          // TN*HN/4 float4s
    float4 v = *(const float4*)&x[(size_t)idx * 4];
    uint2 o;
    o.x = h2u(__float22half2_rn(make_float2(v.x, v.y)));
    o.y = h2u(__float22half2_rn(make_float2(v.z, v.w)));
    *(uint2*)&g_xh[(size_t)idx * 4] = o;
}

// ---------------- router ----------------
__global__ void router_kernel(const float* __restrict__ x, const float* __restrict__ wg) {
    __shared__ float xs[HN];
    __shared__ float logits[EN];
    int t = blockIdx.x;
    for (int i = threadIdx.x; i < HN; i += blockDim.x) xs[i] = x[(size_t)t * HN + i];
    __syncthreads();
    int warp = threadIdx.x >> 5, lane = threadIdx.x & 31;
    for (int e = warp; e < EN; e += 8) {
        const float* w = wg + (size_t)e * HN;
        float s = 0.f;
        for (int i = lane; i < HN; i += 32) s += xs[i] * w[i];
        #pragma unroll
        for (int o = 16; o; o >>= 1) s += __shfl_xor_sync(0xffffffffu, s, o);
        if (lane == 0) logits[e] = s;
    }
    __syncthreads();
    if (threadIdx.x == 0) {
        #pragma unroll 1
        for (int k = 0; k < KN; k++) {
            int best = 0; float bv = -1e30f;
            for (int e = 0; e < EN; e++) {
                float v = logits[e];
                if (v > bv) { bv = v; best = e; }
            }
            logits[best] = -1e30f;
            g_topv[t * KN + k] = 1.f / (1.f + __expf(-bv));
            int slot = atomicAdd(&g_cnt[best], 1);
            g_list[best * TN + slot] = t * KN + k;
        }
    }
}

__global__ void offsets_kernel() {
    if (threadIdx.x == 0) {
        int s = 0;
        for (int e = 0; e < EN; e++) { g_off[e] = s; s += g_cnt[e]; }
    }
}

// ---------------- fp16 tensor-core GEMM ----------------
// C[M,N] = A[M,K] (fp16) * B[N,K]^T (f32 weights, cvt at STS)
// MODE 0: plain rows.  MODE 1: A row = token (g_list>>3), C row compact.
// MODE 2: A row = compact, C row = g_list entry.
// GUFUSE: B rows interleaved (even col=gate row, odd col=up row of w with
//         half-offset hoff); epilogue computes silu(g)*u -> __half C[., hoff].
// CTA tile 128x256x32, 256 threads, warp grid 2x4 (warp tile 64x64).
#define ASTAGE 8192               // A tile: 128 rows x 64 B
#define BSTAGE 16384              // B tile: 256 rows x 64 B
#define STGB   (ASTAGE + BSTAGE)  // 24576
#define SMEM_G (2 * STGB)         // 49152

template <int MODE, bool GUFUSE>
__global__ void __launch_bounds__(256, 1)
gemm_h(const __half* __restrict__ A, const float* __restrict__ Bw,
       void* __restrict__ Cv, int Kdim, int lda, int ldb, int ldc,
       int Mfixed, long long strideB, int hoff)
{
    extern __shared__ char smem[];
    const int tid = threadIdx.x;
    const int e  = blockIdx.z;
    const int m0 = blockIdx.y * 128;
    const int n0 = blockIdx.x * 256;

    int M = Mfixed;
    const float* Bbase = Bw;
    int off_e = 0;
    if (MODE != 0) {
        M = g_cnt[e];
        if (m0 >= M) return;
        Bbase = Bw + (size_t)e * strideB;
        off_e = g_off[e];
    }

    const uint32_t sbase = smem_u32(smem);

    // ---- A (fp16) load mapping: one row, two 16B chunks per thread ----
    const int rA = tid >> 1;
    const int cA = (tid & 1) * 2;
    const __half* pA;
    {
        int gr = m0 + rA;
        int src = (gr < M) ? gr : 0;
        if (MODE == 0)      pA = A + (size_t)gr * lda;
        else if (MODE == 1) pA = A + (size_t)(g_list[e * TN + src] >> 3) * lda;
        else                pA = A + (size_t)(off_e + src) * lda;
        pA += cA * 8;
    }
    const uint32_t soA0 = swz((uint32_t)rA, (uint32_t)cA);
    const uint32_t soA1 = swz((uint32_t)rA, (uint32_t)cA + 1);

    // ---- B (f32) load mapping: 4 rows, one 32B segment per row ----
    const int rbase = tid >> 2;
    const int cseg = tid & 3;
    const float* pB[4];
    uint32_t soB[4];
    #pragma unroll
    for (int j = 0; j < 4; ++j) {
        int r = rbase + j * 64;
        int brow;
        if (GUFUSE) {
            int jg = n0 + r;
            brow = (jg & 1) ? (hoff + (jg >> 1)) : (jg >> 1);
        } else {
            brow = n0 + r;
        }
        pB[j] = Bbase + (size_t)brow * ldb + cseg * 8;
        soB[j] = ASTAGE + swz((uint32_t)r, (uint32_t)cseg);
    }

    // ---- ldmatrix offsets ----
    const int warp = tid >> 5, lane = tid & 31;
    const int wm = warp & 1, wn = warp >> 1;          // 2 x 4 warp grid
    const int l15 = lane & 15, chi = lane >> 4;
    uint32_t aoff[4][2], boff[4][2];
    #pragma unroll
    for (int mf = 0; mf < 4; ++mf) {
        uint32_t r = wm * 64 + mf * 16 + l15;
        #pragma unroll
        for (int ks = 0; ks < 2; ++ks) aoff[mf][ks] = swz(r, ks * 2 + chi);
    }
    #pragma unroll
    for (int np = 0; np < 4; ++np) {
        uint32_t r = wn * 64 + np * 16 + l15;
        #pragma unroll
        for (int ks = 0; ks < 2; ++ks) boff[np][ks] = ASTAGE + swz(r, ks * 2 + chi);
    }

    float acc[4][8][4];
    #pragma unroll
    for (int mf = 0; mf < 4; mf++)
        #pragma unroll
        for (int nf = 0; nf < 8; nf++)
            #pragma unroll
            for (int r = 0; r < 4; r++) acc[mf][nf][r] = 0.f;

    const int nK = Kdim >> 5;

    // staging registers
    uint4 rga[2];
    float4 rgb[4][2];

    auto fetch = [&](int k0) {
        rga[0] = *(const uint4*)(pA + k0);
        rga[1] = *(const uint4*)(pA + k0 + 8);
        #pragma unroll
        for (int j = 0; j < 4; ++j) {
            rgb[j][0] = *(const float4*)(pB[j] + k0);
            rgb[j][1] = *(const float4*)(pB[j] + k0 + 4);
        }
    };
    auto store_stage = [&](uint32_t dst) {
        sts128(dst + soA0, rga[0]);
        sts128(dst + soA1, rga[1]);
        #pragma unroll
        for (int j = 0; j < 4; ++j)
            sts128(dst + soB[j], f8_to_h8(rgb[j][0], rgb[j][1]));
    };

    // prologue: stage 0 -> buf0; stage 1 into regs
    fetch(0);
    store_stage(sbase);
    if (nK > 1) fetch(32);
    __syncthreads();

    for (int kt = 0; kt < nK; ++kt) {
        const uint32_t base = sbase + (uint32_t)(kt & 1) * STGB;
        // store staged regs (stage kt+1) into other buffer, then prefetch kt+2.
        // Safe: end-of-previous-iter sync guarantees no warp still reads that buffer.
        if (kt + 1 < nK) {
            store_stage(sbase + (uint32_t)((kt + 1) & 1) * STGB);
            if (kt + 2 < nK) fetch((kt + 2) << 5);
        }
        #pragma unroll
        for (int ks = 0; ks < 2; ++ks) {
            uint32_t af[4][4], bf[4][4];
            #pragma unroll
            for (int mf = 0; mf < 4; ++mf) ldm4(af[mf], base + aoff[mf][ks]);
            #pragma unroll
            for (int np = 0; np < 4; ++np) ldm4(bf[np], base + boff[np][ks]);
            #pragma unroll
            for (int mf = 0; mf < 4; ++mf)
                #pragma unroll
                for (int nf = 0; nf < 8; ++nf)
                    mma16816(acc[mf][nf], af[mf],
                             bf[nf >> 1][nf & 1], bf[nf >> 1][(nf & 1) | 2]);
        }
        __syncthreads();
    }

    // ---- epilogue ----
    #pragma unroll
    for (int mf = 0; mf < 4; ++mf) {
        #pragma unroll
        for (int half = 0; half < 2; ++half) {
            int rl = wm * 64 + mf * 16 + (lane >> 2) + half * 8;
            int gr = m0 + rl;
            if (gr >= M) continue;
            size_t crow;
            if (MODE == 0)      crow = (size_t)gr;
            else if (MODE == 1) crow = (size_t)(off_e + gr);
            else                crow = (size_t)g_list[e * TN + gr];
            if (GUFUSE) {
                __half* hp = (__half*)Cv + crow * (size_t)hoff
                           + ((n0 + wn * 64) >> 1) + (lane & 3);
                #pragma unroll
                for (int nf = 0; nf < 8; ++nf) {
                    float g = acc[mf][nf][half * 2];
                    float u = acc[mf][nf][half * 2 + 1];
                    float h = g / (1.f + __expf(-g)) * u;
                    hp[nf * 4] = __float2half_rn(h);
                }
            } else {
                float* cp = (float*)Cv + crow * (size_t)ldc + n0 + wn * 64 + (lane & 3) * 2;
                #pragma unroll
                for (int nf = 0; nf < 8; ++nf) {
                    float2 v = make_float2(acc[mf][nf][half * 2], acc[mf][nf][half * 2 + 1]);
                    *(float2*)(cp + nf * 8) = v;
                }
            }
        }
    }
}

// ---------------- combine ----------------
__global__ void combine_kernel(float* __restrict__ out) {
    int idx = blockIdx.x * 256 + threadIdx.x;          // over [1024 * 512] float4
    int t = idx >> 9, d = (idx & 511) * 4;
    float4 acc = make_float4(0.f, 0.f, 0.f, 0.f);
    #pragma unroll
    for (int k = 0; k < KN; k++) {
        float w = g_topv[t * KN + k];
        float4 m = *(const float4*)&g_moe[(size_t)(t * KN + k) * HN + d];
        acc.x += w * m.x; acc.y += w * m.y; acc.z += w * m.z; acc.w += w * m.w;
    }
    float4 s = *(const float4*)&g_sh[(size_t)t * HN + d];
    const float inv = 1.f / (float)(KN + 1);
    float4 o;
    o.x = (s.x + KN * acc.x) * inv;
    o.y = (s.y + KN * acc.y) * inv;
    o.z = (s.z + KN * acc.z) * inv;
    o.w = (s.w + KN * acc.w) * inv;
    *(float4*)&out[(size_t)t * HN + d] = o;
}

// ---------------- launch ----------------
extern "C" void kernel_launch(void* const* d_in, const int* in_sizes, int n_in,
                              void* d_out, int out_size)
{
    const float* x      = (const float*)d_in[0];  // [T,H]
    const float* w_gate = (const float*)d_in[1];  // [E,H]
    const float* w13    = (const float*)d_in[2];  // [E,2I,H]
    const float* w2     = (const float*)d_in[3];  // [E,H,I]
    const float* w_sgu  = (const float*)d_in[4];  // [2SI,H]
    const float* w_sdn  = (const float*)d_in[5];  // [H,SI]
    float* out = (float*)d_out;

    cudaFuncSetAttribute(gemm_h<0,false>, cudaFuncAttributeMaxDynamicSharedMemorySize, SMEM_G);
    cudaFuncSetAttribute(gemm_h<0,true>,  cudaFuncAttributeMaxDynamicSharedMemorySize, SMEM_G);
    cudaFuncSetAttribute(gemm_h<1,true>,  cudaFuncAttributeMaxDynamicSharedMemorySize, SMEM_G);
    cudaFuncSetAttribute(gemm_h<2,false>, cudaFuncAttributeMaxDynamicSharedMemorySize, SMEM_G);

    __half *xh, *h, *hs;
    float *moe, *sh;
    cudaGetSymbolAddress((void**)&xh,  g_xh);
    cudaGetSymbolAddress((void**)&h,   g_h);
    cudaGetSymbolAddress((void**)&hs,  g_hs);
    cudaGetSymbolAddress((void**)&moe, g_moe);
    cudaGetSymbolAddress((void**)&sh,  g_sh);

    zero_cnt_kernel<<<1, 64>>>();
    cvt_x_kernel<<<(TN * HN / 4) / 256, 256>>>(x);
    router_kernel<<<TN, 256>>>(x, w_gate);
    offsets_kernel<<<1, 32>>>();

    // expert gate_up + silu fused: A=xh gathered, B=w13[e] interleaved, C=g_h fp16
    gemm_h<1,true><<<dim3(2 * IN / 256, 8, EN), 256, SMEM_G>>>(
        xh, w13, h, HN, HN, HN, 0, 0, (long long)2 * IN * HN, IN);

    // expert down: A=g_h compact (fp16), B=w2[e], C=g_moe scatter
    gemm_h<2,false><<<dim3(HN / 256, 8, EN), 256, SMEM_G>>>(
        h, w2, moe, IN, IN, IN, HN, 0, (long long)HN * IN, 0);

    // shared gate_up + silu fused: A=xh, B=w_sgu interleaved, C=g_hs fp16
    gemm_h<0,true><<<dim3(2 * SIN / 256, TN / 128, 1), 256, SMEM_G>>>(
        xh, w_sgu, hs, HN, HN, HN, 0, TN, 0, SIN);

    // shared down: A=g_hs (fp16), B=w_sdn, C=g_sh
    gemm_h<0,false><<<dim3(HN / 256, TN / 128, 1), 256, SMEM_G>>>(
        hs, w_sdn, sh, SIN, SIN, SIN, HN, TN, 0, 0);

    combine_kernel<<<(TN * HN / 4) / 256, 256>>>(out);
}